// round 3
// baseline (speedup 1.0000x reference)
#include <cuda_runtime.h>
#include <cstdint>
#include <math.h>

#define BB 128
#define SS 2048
#define TTAGS 64

__device__ float g_part[BB];
__device__ float g_score[BB];

// Detect how the bool mask was materialized by the harness.
// 0 -> 1-byte elements (uint8/bool), 1 -> 4-byte elements (int32 or float32).
__device__ __forceinline__ int mask_mode_of(const void* m)
{
    uint32_t w0 = *(const uint32_t*)m;
    if (w0 == 0x01010101u) return 0;   // bytes of ones
    if (w0 == 0x3F800000u) return 1;   // float 1.0f
    if ((w0 >> 8) == 0u)   return 1;   // int32 0/1 pattern
    return 0;
}

// ---------------------------------------------------------------------------
// Partition function: one block per batch, 64 threads (2 warps), thread j owns
// state j. Linear-space forward recurrence
//     q'(j) = (sum_i q(i) * exp(T[i][j] - c_j)) * exp(em[t][j] + c_j)
// Exact power-of-two renorm every step using exponent(q_prev[0]) (register-
// resident from the q reload) -> no reductions / extra barriers in the loop.
// Invariant: alpha_t = q_t * 2^esum  (exact bookkeeping, pow2 scales only).
// Emissions pipeline: raw loads 8..24 steps ahead; __expf conversion 8 steps
// ahead, one per step, off the serial dependency chain.
// ---------------------------------------------------------------------------
__global__ void __launch_bounds__(64, 1) crf_part_kernel(
    const float* __restrict__ em,
    const void* __restrict__ maskv,
    const float* __restrict__ trans,
    const float* __restrict__ startt,
    const float* __restrict__ endt)
{
    __shared__ __align__(16) float qs[2][TTAGS];
    __shared__ float wred[2];
    __shared__ unsigned char msk[SS];

    const int j = threadIdx.x;
    const int b = blockIdx.x;
    const int w = j >> 5;
    const int lane = j & 31;

    // ---- stage mask row into shared as bytes ----
    const int mmode = mask_mode_of(maskv);
    if (mmode == 0) {
        const uint32_t* m32 =
            (const uint32_t*)((const unsigned char*)maskv + (size_t)b * SS);
        uint32_t* s32 = (uint32_t*)msk;
        #pragma unroll
        for (int i = 0; i < (SS / 4) / TTAGS; i++)      // 8 iters
            s32[j + i * TTAGS] = m32[j + i * TTAGS];
    } else {
        const uint32_t* m32 = (const uint32_t*)maskv + (size_t)b * SS;
        #pragma unroll
        for (int i = 0; i < SS / TTAGS; i++)            // 32 iters
            msk[j + i * TTAGS] = (m32[j + i * TTAGS] != 0u) ? 1 : 0;
    }

    // ---- column max of transitions: c_j = max_i T[i][j] ----
    float c = -3.0e38f;
    #pragma unroll
    for (int i = 0; i < TTAGS; i++) c = fmaxf(c, trans[i * TTAGS + j]);

    // ---- Ê column in registers, packed f32x2 over i ----
    unsigned long long epk[TTAGS / 2];
    #pragma unroll
    for (int k = 0; k < TTAGS / 2; k++) {
        float e0 = __expf(trans[(2 * k) * TTAGS + j] - c);
        float e1 = __expf(trans[(2 * k + 1) * TTAGS + j] - c);
        epk[k] = (unsigned long long)__float_as_uint(e0) |
                 ((unsigned long long)__float_as_uint(e1) << 32);
    }

    const float* emb = em + (size_t)b * SS * TTAGS + j;

    // alpha0 = start + em[:,0], linear space
    float qreg = __expf(startt[j] + emb[0]);
    qs[0][j] = qreg;
    int esum = 0;    // exact pow2 renorm exponent accumulator
    int sb = 0;      // q double-buffer parity
    __syncthreads();

    // ---- one forward step (FV = precomputed exp(em+c)) ----
#define CRF_STEP(FV, TTI)                                                        \
    do {                                                                         \
        int mv = msk[(TTI)];                                                     \
        const ulonglong2* qv = (const ulonglong2*)qs[sb];                        \
        unsigned long long a0 = 0ull, a1 = 0ull, a2 = 0ull, a3 = 0ull;           \
        unsigned long long a4 = 0ull, a5 = 0ull, a6 = 0ull, a7 = 0ull;           \
        uint32_t q0b = 0;                                                        \
        _Pragma("unroll")                                                        \
        for (int k2 = 0; k2 < 8; k2++) {                                         \
            ulonglong2 v0 = qv[2 * k2];                                          \
            ulonglong2 v1 = qv[2 * k2 + 1];                                      \
            if (k2 == 0) q0b = (uint32_t)v0.x;                                   \
            if ((k2 & 1) == 0) {                                                 \
                asm("fma.rn.f32x2 %0, %1, %2, %0;" : "+l"(a0) : "l"(v0.x), "l"(epk[4*k2+0])); \
                asm("fma.rn.f32x2 %0, %1, %2, %0;" : "+l"(a1) : "l"(v0.y), "l"(epk[4*k2+1])); \
                asm("fma.rn.f32x2 %0, %1, %2, %0;" : "+l"(a2) : "l"(v1.x), "l"(epk[4*k2+2])); \
                asm("fma.rn.f32x2 %0, %1, %2, %0;" : "+l"(a3) : "l"(v1.y), "l"(epk[4*k2+3])); \
            } else {                                                             \
                asm("fma.rn.f32x2 %0, %1, %2, %0;" : "+l"(a4) : "l"(v0.x), "l"(epk[4*k2+0])); \
                asm("fma.rn.f32x2 %0, %1, %2, %0;" : "+l"(a5) : "l"(v0.y), "l"(epk[4*k2+1])); \
                asm("fma.rn.f32x2 %0, %1, %2, %0;" : "+l"(a6) : "l"(v1.x), "l"(epk[4*k2+2])); \
                asm("fma.rn.f32x2 %0, %1, %2, %0;" : "+l"(a7) : "l"(v1.y), "l"(epk[4*k2+3])); \
            }                                                                    \
        }                                                                        \
        asm("add.rn.f32x2 %0, %0, %1;" : "+l"(a0) : "l"(a4));                    \
        asm("add.rn.f32x2 %0, %0, %1;" : "+l"(a1) : "l"(a5));                    \
        asm("add.rn.f32x2 %0, %0, %1;" : "+l"(a2) : "l"(a6));                    \
        asm("add.rn.f32x2 %0, %0, %1;" : "+l"(a3) : "l"(a7));                    \
        asm("add.rn.f32x2 %0, %0, %1;" : "+l"(a0) : "l"(a1));                    \
        asm("add.rn.f32x2 %0, %0, %1;" : "+l"(a2) : "l"(a3));                    \
        asm("add.rn.f32x2 %0, %0, %1;" : "+l"(a0) : "l"(a2));                    \
        float accf = __uint_as_float((uint32_t)a0) +                             \
                     __uint_as_float((uint32_t)(a0 >> 32));                      \
        float tj = accf * (FV);                                                  \
        float qn = mv ? tj : qreg;                                               \
        int e = (int)((q0b >> 23) & 0xffu) - 127;                                \
        qn *= __int_as_float((127 - e) << 23);                                   \
        esum += e;                                                               \
        qreg = qn;                                                               \
        qs[sb ^ 1][j] = qn;                                                      \
        __syncthreads();                                                         \
        sb ^= 1;                                                                 \
    } while (0)

#define CRF_LOADR(BUF, TB)                                                       \
    do {                                                                         \
        _Pragma("unroll")                                                        \
        for (int g = 0; g < 8; g++) {                                            \
            int tt = (TB) + g;                                                   \
            int ttc = tt < SS ? tt : (SS - 1);                                   \
            BUF[g] = emb[(size_t)ttc * TTAGS];                                   \
        }                                                                        \
    } while (0)

// Process 8 steps from FBUF; interleave conversion of the NEXT group's raw
// emissions (RNEXT) into FNEXT, one __expf per step (off the serial chain).
#define CRF_GROUP(FBUF, RNEXT, FNEXT, TB)                                        \
    do {                                                                         \
        _Pragma("unroll")                                                        \
        for (int g = 0; g < 8; g++) {                                            \
            FNEXT[g] = __expf(RNEXT[g] + c);                                     \
            int tt = (TB) + g;                                                   \
            if (tt < SS) { CRF_STEP(FBUF[g], tt); }                              \
        }                                                                        \
    } while (0)

    float fA[8], fB[8], rawA[8], rawB[8];

    // startup: F for t=1..8 (startup stall OK), raw loads for t=9..16
    CRF_LOADR(rawA, 1);
    #pragma unroll
    for (int g = 0; g < 8; g++) fA[g] = __expf(rawA[g] + c);
    CRF_LOADR(rawB, 9);

    // steps t = 1 .. 2047 (t = 2048 guarded off in the last iteration)
    for (int it = 0; it < 128; it++) {
        const int base = 1 + it * 16;
        CRF_LOADR(rawA, base + 16);
        CRF_GROUP(fA, rawB, fB, base);
        CRF_LOADR(rawB, base + 24);
        CRF_GROUP(fB, rawA, fA, base + 8);
    }

    // logZ = log(sum_j q_j * exp(end_j)) + esum*ln2
    float v = qreg * __expf(endt[j]);
    #pragma unroll
    for (int o = 16; o > 0; o >>= 1)
        v += __shfl_xor_sync(0xffffffffu, v, o);
    if (lane == 0) wred[w] = v;
    __syncthreads();
    if (j == 0)
        g_part[b] = (float)(log((double)(wred[0] + wred[1])) +
                            (double)esum * 0.6931471805599453);

#undef CRF_STEP
#undef CRF_LOADR
#undef CRF_GROUP
}

// ---------------------------------------------------------------------------
// Gold-path score: one warp per batch. Reference uses transitions[cur, prev]
// here (vs T[prev, cur] in the recurrence) — reproduced faithfully.
// ---------------------------------------------------------------------------
__global__ void __launch_bounds__(32, 1) crf_score_kernel(
    const float* __restrict__ em,
    const int* __restrict__ tags,
    const void* __restrict__ maskv,
    const float* __restrict__ trans,
    const float* __restrict__ startt,
    const float* __restrict__ endt)
{
    const int b = blockIdx.x, lane = threadIdx.x;
    const int* tg = tags + (size_t)b * SS;
    const float* emb = em + (size_t)b * SS * TTAGS;

    const int mmode = mask_mode_of(maskv);
    const unsigned char* mb8 = (const unsigned char*)maskv + (size_t)b * SS;
    const uint32_t* mb32 = (const uint32_t*)maskv + (size_t)b * SS;

    float s = 0.f;
    int cnt = 0;
    for (int i = lane; i < SS; i += 32) {
        int tc = tg[i];
        int m = (mmode == 0) ? (mb8[i] != 0) : (mb32[i] != 0u);
        cnt += m;
        if (i == 0) {
            s += startt[tc] + emb[tc];
        } else if (m) {
            s += trans[tc * TTAGS + tg[i - 1]] + emb[(size_t)i * TTAGS + tc];
        }
    }
    #pragma unroll
    for (int o = 16; o > 0; o >>= 1) {
        s += __shfl_xor_sync(0xffffffffu, s, o);
        cnt += __shfl_xor_sync(0xffffffffu, cnt, o);
    }
    if (lane == 0) {
        int last = cnt > 0 ? cnt - 1 : 0;
        g_score[b] = s + endt[tg[last]];
    }
}

// ---------------------------------------------------------------------------
// out = mean(partition - score)  ==  -(score - partition).mean()
// ---------------------------------------------------------------------------
__global__ void crf_final_kernel(float* __restrict__ out)
{
    const int i = threadIdx.x;  // 128 threads
    double v = (double)g_part[i] - (double)g_score[i];
    #pragma unroll
    for (int o = 16; o > 0; o >>= 1)
        v += __shfl_xor_sync(0xffffffffu, v, o);
    __shared__ double sm[4];
    if ((i & 31) == 0) sm[i >> 5] = v;
    __syncthreads();
    if (i == 0)
        out[0] = (float)((sm[0] + sm[1] + sm[2] + sm[3]) * (1.0 / (double)BB));
}

extern "C" void kernel_launch(void* const* d_in, const int* in_sizes, int n_in,
                              void* d_out, int out_size)
{
    const float* em     = (const float*)d_in[0];
    const int* tags     = (const int*)d_in[1];
    const void* mask    = (const void*)d_in[2];
    const float* trans  = (const float*)d_in[3];
    const float* startt = (const float*)d_in[4];
    const float* endt   = (const float*)d_in[5];

    crf_part_kernel<<<BB, 64>>>(em, mask, trans, startt, endt);
    crf_score_kernel<<<BB, 32>>>(em, tags, mask, trans, startt, endt);
    crf_final_kernel<<<1, 128>>>((float*)d_out);
}

// round 5
// speedup vs baseline: 1.0519x; 1.0519x over previous
#include <cuda_runtime.h>
#include <cstdint>
#include <math.h>

#define BB 128
#define SS 2048
#define TTAGS 64

__device__ float g_part[BB];
__device__ float g_score[BB];

// 0 -> 1-byte mask elements (uint8/bool), 1 -> 4-byte (int32/float32).
__device__ __forceinline__ int mask_mode_of(const void* m)
{
    uint32_t w0 = *(const uint32_t*)m;
    if (w0 == 0x01010101u) return 0;
    if (w0 == 0x3F800000u) return 1;
    if ((w0 >> 8) == 0u)   return 1;
    return 0;
}

#define PART_BAR() asm volatile("bar.sync 1, 128;" ::: "memory")

// ---------------------------------------------------------------------------
// Fused partition + score kernel. 160 threads:
//   threads 0..127 (4 warps): forward partition recurrence, split-K x2.
//     lane pair (l, l+16) of warp w owns state j = w*16 + (l&15);
//     lane half h = l>>4 computes the 32-term half-dot over i in [h*32,h*32+32),
//     halves combined with shfl_xor(16). One bar.sync(1,128) per step.
//   threads 128..159 (warp 4): gold-path score (independent, never hits bar 1).
// Linear space: q'(j) = (sum_i q(i)*exp(T[i][j]-c_j)) * exp(em[t][j]+c_j),
// exact pow2 renorm every 4 steps via exponent(q_prev[0]).
// q layout: lo half states 0..31 at bytes [0,128), hi states 32..63 at
// [144,272) (16B pad -> the two broadcast groups of each LDS.128 hit
// disjoint banks).
// ---------------------------------------------------------------------------
__global__ void __launch_bounds__(160, 1) crf_part_score_kernel(
    const float* __restrict__ em,
    const int* __restrict__ tags,
    const void* __restrict__ maskv,
    const float* __restrict__ trans,
    const float* __restrict__ startt,
    const float* __restrict__ endt)
{
    __shared__ __align__(16) float qs0[68];
    __shared__ __align__(16) float qs1[68];
    __shared__ float wred[4];
    __shared__ unsigned char msk[SS];

    const int t = threadIdx.x;
    const int b = blockIdx.x;
    const int mmode = mask_mode_of(maskv);

    // ================= score warp (threads 128..159) =================
    if (t >= 128) {
        const int lane = t - 128;
        const int* tg = tags + (size_t)b * SS;
        const float* emb = em + (size_t)b * SS * TTAGS;
        const unsigned char* mb8 = (const unsigned char*)maskv + (size_t)b * SS;
        const uint32_t* mb32 = (const uint32_t*)maskv + (size_t)b * SS;

        float s = 0.f;
        int cnt = 0;
        for (int i = lane; i < SS; i += 32) {
            int tc = tg[i];
            int m = (mmode == 0) ? (mb8[i] != 0) : (mb32[i] != 0u);
            cnt += m;
            if (i == 0) {
                s += startt[tc] + emb[tc];
            } else if (m) {
                s += trans[tc * TTAGS + tg[i - 1]] + emb[(size_t)i * TTAGS + tc];
            }
        }
        #pragma unroll
        for (int o = 16; o > 0; o >>= 1) {
            s += __shfl_xor_sync(0xffffffffu, s, o);
            cnt += __shfl_xor_sync(0xffffffffu, cnt, o);
        }
        if (lane == 0) {
            int last = cnt > 0 ? cnt - 1 : 0;
            g_score[b] = s + endt[tg[last]];
        }
        return;
    }

    // ================= partition warps (threads 0..127) =================
    const int w = t >> 5;
    const int l = t & 31;
    const int j = w * 16 + (l & 15);        // state owned by this lane pair
    const int h = l >> 4;                   // which half of the dot product
    const int sidx = j + ((j >> 5) << 2);   // padded storage index
    const uint32_t hoff = (uint32_t)h * 144;

    // ---- stage mask row into shared as bytes (128 threads) ----
    if (mmode == 0) {
        const uint32_t* m32 =
            (const uint32_t*)((const unsigned char*)maskv + (size_t)b * SS);
        uint32_t* s32 = (uint32_t*)msk;
        #pragma unroll
        for (int i = 0; i < (SS / 4) / 128; i++)     // 4 iters
            s32[t + i * 128] = m32[t + i * 128];
    } else {
        const uint32_t* m32 = (const uint32_t*)maskv + (size_t)b * SS;
        #pragma unroll
        for (int i = 0; i < SS / 128; i++)           // 16 iters
            msk[t + i * 128] = (m32[t + i * 128] != 0u) ? 1 : 0;
    }

    // ---- column max c_j = max_i T[i][j] ----
    float c = -3.0e38f;
    #pragma unroll
    for (int i = 0; i < TTAGS; i++) c = fmaxf(c, trans[i * TTAGS + j]);

    // ---- Ê half-column in registers: i in [h*32, h*32+32), packed pairs ----
    unsigned long long epk[16];
    #pragma unroll
    for (int k = 0; k < 16; k++) {
        int i0 = h * 32 + 2 * k;
        float e0 = __expf(trans[i0 * TTAGS + j] - c);
        float e1 = __expf(trans[(i0 + 1) * TTAGS + j] - c);
        epk[k] = (unsigned long long)__float_as_uint(e0) |
                 ((unsigned long long)__float_as_uint(e1) << 32);
    }

    const float* emb = em + (size_t)b * SS * TTAGS + j;

    // alpha0 (both halves compute the same value; h==0 stores)
    float qreg = __expf(startt[j] + emb[0]);
    if (h == 0) qs0[sidx] = qreg;
    int esum = 0;
    PART_BAR();

    // ---- one forward step ----
#define CRF_STEP(QSRC, QDST, FV, TTI, DOREN)                                     \
    do {                                                                         \
        int mv = msk[(TTI)];                                                     \
        uint32_t q0w = 0;                                                        \
        if (DOREN) q0w = *(const uint32_t*)(QSRC);                               \
        const ulonglong2* qv =                                                   \
            (const ulonglong2*)((const char*)(QSRC) + hoff);                     \
        unsigned long long a0 = 0ull, a1 = 0ull, a2 = 0ull, a3 = 0ull;           \
        _Pragma("unroll")                                                        \
        for (int k2 = 0; k2 < 4; k2++) {                                         \
            ulonglong2 v0 = qv[2 * k2];                                          \
            ulonglong2 v1 = qv[2 * k2 + 1];                                      \
            asm("fma.rn.f32x2 %0, %1, %2, %0;" : "+l"(a0) : "l"(v0.x), "l"(epk[4*k2+0])); \
            asm("fma.rn.f32x2 %0, %1, %2, %0;" : "+l"(a1) : "l"(v0.y), "l"(epk[4*k2+1])); \
            asm("fma.rn.f32x2 %0, %1, %2, %0;" : "+l"(a2) : "l"(v1.x), "l"(epk[4*k2+2])); \
            asm("fma.rn.f32x2 %0, %1, %2, %0;" : "+l"(a3) : "l"(v1.y), "l"(epk[4*k2+3])); \
        }                                                                        \
        asm("add.rn.f32x2 %0, %0, %1;" : "+l"(a0) : "l"(a1));                    \
        asm("add.rn.f32x2 %0, %0, %1;" : "+l"(a2) : "l"(a3));                    \
        asm("add.rn.f32x2 %0, %0, %1;" : "+l"(a0) : "l"(a2));                    \
        float accf = __uint_as_float((uint32_t)a0) +                             \
                     __uint_as_float((uint32_t)(a0 >> 32));                      \
        float tot = accf + __shfl_xor_sync(0xffffffffu, accf, 16);               \
        float tj = tot * (FV);                                                   \
        float qn = mv ? tj : qreg;                                               \
        if (DOREN) {                                                             \
            int e = (int)((q0w >> 23) & 0xffu) - 127;                            \
            qn *= __int_as_float((127 - e) << 23);                               \
            esum += e;                                                           \
        }                                                                        \
        qreg = qn;                                                               \
        if (h == 0) (QDST)[sidx] = qn;                                           \
        PART_BAR();                                                              \
    } while (0)

#define CRF_LOADR(BUF, TB)                                                       \
    do {                                                                         \
        _Pragma("unroll")                                                        \
        for (int g = 0; g < 8; g++) {                                            \
            int tt = (TB) + g;                                                   \
            int ttc = tt < SS ? tt : (SS - 1);                                   \
            BUF[g] = emb[(size_t)ttc * TTAGS];                                   \
        }                                                                        \
    } while (0)

// 8 steps from FBUF starting at qs0 parity; interleave next group's __expf.
#define CRF_GROUP(FBUF, RNEXT, FNEXT, TB)                                        \
    do {                                                                         \
        _Pragma("unroll")                                                        \
        for (int g = 0; g < 8; g += 2) {                                         \
            FNEXT[g] = __expf(RNEXT[g] + c);                                     \
            int t0 = (TB) + g;                                                   \
            if (t0 < SS) { CRF_STEP(qs0, qs1, FBUF[g], t0, ((g & 3) == 0)); }    \
            FNEXT[g + 1] = __expf(RNEXT[g + 1] + c);                             \
            int t1 = (TB) + g + 1;                                               \
            if (t1 < SS) { CRF_STEP(qs1, qs0, FBUF[g + 1], t1, 0); }             \
        }                                                                        \
    } while (0)

    float fA[8], fB[8], rawA[8], rawB[8];

    CRF_LOADR(rawA, 1);
    #pragma unroll
    for (int g = 0; g < 8; g++) fA[g] = __expf(rawA[g] + c);
    CRF_LOADR(rawB, 9);

    // steps t = 1 .. 2047 (t = 2048 guarded off).
    // unroll 1: body is ~13KB of SASS; unrolling would spill out of L1.5 I$.
    #pragma unroll 1
    for (int it = 0; it < 128; it++) {
        const int base = 1 + it * 16;
        CRF_LOADR(rawA, base + 16);
        CRF_GROUP(fA, rawB, fB, base);
        CRF_LOADR(rawB, base + 24);
        CRF_GROUP(fB, rawA, fA, base + 8);
    }

    // logZ = log(sum_j q_j * exp(end_j)) + esum*ln2
    float v = (h == 0) ? qreg * __expf(endt[j]) : 0.f;
    #pragma unroll
    for (int o = 16; o > 0; o >>= 1)
        v += __shfl_xor_sync(0xffffffffu, v, o);
    if (l == 0) wred[w] = v;
    PART_BAR();
    if (t == 0)
        g_part[b] = (float)(log((double)(wred[0] + wred[1] + wred[2] + wred[3])) +
                            (double)esum * 0.6931471805599453);

#undef CRF_STEP
#undef CRF_LOADR
#undef CRF_GROUP
}

// ---------------------------------------------------------------------------
// out = mean(partition - score)
// ---------------------------------------------------------------------------
__global__ void crf_final_kernel(float* __restrict__ out)
{
    const int i = threadIdx.x;  // 128 threads
    double v = (double)g_part[i] - (double)g_score[i];
    #pragma unroll
    for (int o = 16; o > 0; o >>= 1)
        v += __shfl_xor_sync(0xffffffffu, v, o);
    __shared__ double sm[4];
    if ((i & 31) == 0) sm[i >> 5] = v;
    __syncthreads();
    if (i == 0)
        out[0] = (float)((sm[0] + sm[1] + sm[2] + sm[3]) * (1.0 / (double)BB));
}

extern "C" void kernel_launch(void* const* d_in, const int* in_sizes, int n_in,
                              void* d_out, int out_size)
{
    const float* em     = (const float*)d_in[0];
    const int* tags     = (const int*)d_in[1];
    const void* mask    = (const void*)d_in[2];
    const float* trans  = (const float*)d_in[3];
    const float* startt = (const float*)d_in[4];
    const float* endt   = (const float*)d_in[5];

    crf_part_score_kernel<<<BB, 160>>>(em, tags, mask, trans, startt, endt);
    crf_final_kernel<<<1, 128>>>((float*)d_out);
}

// round 7
// speedup vs baseline: 1.1462x; 1.0896x over previous
#include <cuda_runtime.h>
#include <cstdint>
#include <math.h>

#define BB 128
#define SS 2048
#define TTAGS 64

__device__ float g_part[BB];
__device__ float g_score[BB];

// 0 -> 1-byte mask elements (uint8/bool), 1 -> 4-byte (int32/float32).
__device__ __forceinline__ int mask_mode_of(const void* m)
{
    uint32_t w0 = *(const uint32_t*)m;
    if (w0 == 0x01010101u) return 0;
    if (w0 == 0x3F800000u) return 1;
    if ((w0 >> 8) == 0u)   return 1;
    return 0;
}

// 160 participants: 4 consumer warps + 1 producer warp. Score warp excluded.
#define PART_BAR() asm volatile("bar.sync 1, 160;" ::: "memory")

// ---------------------------------------------------------------------------
// Fused kernel, 192 threads / block, one block per batch:
//   warps 0..3 (consumers): forward recurrence, split-K x2. Lane pair
//     (l, l+16) of warp w owns state j = w*16 + (l&15); half h = l>>4 does the
//     32-term half-dot, combined by shfl_xor(16). One bar.sync(1,160)/step.
//   warp 4 (producer): streams emissions and writes F_t[j] = exp(em+c_j) into
//     a 16-deep shared ring, 15 rounds ahead; joins the same barrier.
//   warp 5 (score): gold-path score, independent, never touches bar 1.
// Linear space: q'(j) = (sum_i q(i)*exp(T[i][j]-c_j)) * F_t(j);
// exact pow2 renorm every 4 steps via exponent(q_prev[0]).
// ---------------------------------------------------------------------------
__global__ void __launch_bounds__(192, 1) crf_part_score_kernel(
    const float* __restrict__ em,
    const int* __restrict__ tags,
    const void* __restrict__ maskv,
    const float* __restrict__ trans,
    const float* __restrict__ startt,
    const float* __restrict__ endt)
{
    __shared__ __align__(16) float qs0[68];
    __shared__ __align__(16) float qs1[68];
    __shared__ __align__(16) float ringF[16][TTAGS];   // 4KB F ring
    __shared__ float wred[4];
    __shared__ unsigned char msk[SS];

    const int t = threadIdx.x;
    const int b = blockIdx.x;
    const int mmode = mask_mode_of(maskv);

    // ================= score warp (threads 160..191) =================
    if (t >= 160) {
        const int lane = t - 160;
        const int* tg = tags + (size_t)b * SS;
        const float* emb = em + (size_t)b * SS * TTAGS;
        const unsigned char* mb8 = (const unsigned char*)maskv + (size_t)b * SS;
        const uint32_t* mb32 = (const uint32_t*)maskv + (size_t)b * SS;

        float s = 0.f;
        int cnt = 0;
        for (int i = lane; i < SS; i += 32) {
            int tc = tg[i];
            int m = (mmode == 0) ? (mb8[i] != 0) : (mb32[i] != 0u);
            cnt += m;
            if (i == 0) {
                s += startt[tc] + emb[tc];
            } else if (m) {
                s += trans[tc * TTAGS + tg[i - 1]] + emb[(size_t)i * TTAGS + tc];
            }
        }
        #pragma unroll
        for (int o = 16; o > 0; o >>= 1) {
            s += __shfl_xor_sync(0xffffffffu, s, o);
            cnt += __shfl_xor_sync(0xffffffffu, cnt, o);
        }
        if (lane == 0) {
            int last = cnt > 0 ? cnt - 1 : 0;
            g_score[b] = s + endt[tg[last]];
        }
        return;
    }

    // ================= producer warp (threads 128..159) =================
    if (t >= 128) {
        const int p = t - 128;           // 0..31, owns states 2p, 2p+1
        const int j0 = 2 * p;

        float c0 = -3.0e38f, c1 = -3.0e38f;
        #pragma unroll
        for (int i = 0; i < TTAGS; i++) {
            c0 = fmaxf(c0, trans[i * TTAGS + j0]);
            c1 = fmaxf(c1, trans[i * TTAGS + j0 + 1]);
        }

        const float2* embp =
            (const float2*)(em + (size_t)b * SS * TTAGS + j0);  // [t] -> pair

        // prefill F(1..15) synchronously
        #pragma unroll
        for (int u = 1; u < 16; u++) {
            float2 r = embp[(size_t)u * (TTAGS / 2)];
            *(float2*)&ringF[u][j0] =
                make_float2(__expf(r.x + c0), __expf(r.y + c1));
        }

#define P_LOADR(BUF, U0)                                                         \
        do {                                                                     \
            _Pragma("unroll")                                                    \
            for (int g = 0; g < 8; g++) {                                        \
                int u = (U0) + g;                                                \
                int uc = u < SS ? u : (SS - 1);                                  \
                BUF[g] = embp[(size_t)uc * (TTAGS / 2)];                         \
            }                                                                    \
        } while (0)

        float2 rA[8], rB[8];
        P_LOADR(rA, 16);     // raws for steps 16..23
        P_LOADR(rB, 24);     // raws for steps 24..31
        PART_BAR();          // init barrier (matches consumers)

        // rounds t = 1+it*16+k; at round t produce F(t+15)
        #pragma unroll 1
        for (int it = 0; it < 128; it++) {
            const int rbase = 1 + it * 16;   // first round of this group
            const int pbase = rbase + 15;    // first produced step
            #pragma unroll
            for (int k = 0; k < 8; k++) {
                int rt = rbase + k;
                int u  = pbase + k;          // slot = (pbase+k)&15 = k
                if (rt < SS) {
                    if (u < SS)
                        *(float2*)&ringF[k][j0] =
                            make_float2(__expf(rA[k].x + c0), __expf(rA[k].y + c1));
                    PART_BAR();
                }
            }
            P_LOADR(rA, pbase + 16);
            #pragma unroll
            for (int k = 0; k < 8; k++) {
                int rt = rbase + 8 + k;
                int u  = pbase + 8 + k;      // slot = 8+k
                if (rt < SS) {
                    if (u < SS)
                        *(float2*)&ringF[8 + k][j0] =
                            make_float2(__expf(rB[k].x + c0), __expf(rB[k].y + c1));
                    PART_BAR();
                }
            }
            P_LOADR(rB, pbase + 24);
        }
        PART_BAR();          // matches consumers' final reduce barrier
        return;
#undef P_LOADR
    }

    // ================= consumer warps (threads 0..127) =================
    const int w = t >> 5;
    const int l = t & 31;
    const int j = w * 16 + (l & 15);        // state owned by this lane pair
    const int h = l >> 4;                   // dot-product half
    const int sidx = j + ((j >> 5) << 2);   // padded q index
    const uint32_t hoff = (uint32_t)h * 144;

    // ---- stage mask row into shared as bytes ----
    if (mmode == 0) {
        const uint32_t* m32 =
            (const uint32_t*)((const unsigned char*)maskv + (size_t)b * SS);
        uint32_t* s32 = (uint32_t*)msk;
        #pragma unroll
        for (int i = 0; i < (SS / 4) / 128; i++)
            s32[t + i * 128] = m32[t + i * 128];
    } else {
        const uint32_t* m32 = (const uint32_t*)maskv + (size_t)b * SS;
        #pragma unroll
        for (int i = 0; i < SS / 128; i++)
            msk[t + i * 128] = (m32[t + i * 128] != 0u) ? 1 : 0;
    }

    // ---- column max c_j (same scan order as producer -> bitwise equal) ----
    float c = -3.0e38f;
    #pragma unroll
    for (int i = 0; i < TTAGS; i++) c = fmaxf(c, trans[i * TTAGS + j]);

    // ---- Ê half-column: i in [h*32, h*32+32), packed f32x2 pairs ----
    unsigned long long epk[16];
    #pragma unroll
    for (int k = 0; k < 16; k++) {
        int i0 = h * 32 + 2 * k;
        float e0 = __expf(trans[i0 * TTAGS + j] - c);
        float e1 = __expf(trans[(i0 + 1) * TTAGS + j] - c);
        epk[k] = (unsigned long long)__float_as_uint(e0) |
                 ((unsigned long long)__float_as_uint(e1) << 32);
    }

    // alpha0 (both halves compute; h==0 stores)
    float qreg = __expf(startt[j] + em[(size_t)b * SS * TTAGS + j]);
    if (h == 0) qs0[sidx] = qreg;
    int esum = 0;
    PART_BAR();   // init barrier

    // ---- one forward step; SL = compile-time ring slot ----
#define CRF_STEP(QSRC, QDST, TTI, SL, DOREN)                                     \
    do {                                                                         \
        int mv = msk[(TTI)];                                                     \
        float Fv = ringF[(SL)][j];                                               \
        uint32_t q0w = 0;                                                        \
        if (DOREN) q0w = *(const uint32_t*)(QSRC);                               \
        const ulonglong2* qv =                                                   \
            (const ulonglong2*)((const char*)(QSRC) + hoff);                     \
        unsigned long long a0 = 0ull, a1 = 0ull, a2 = 0ull, a3 = 0ull;           \
        _Pragma("unroll")                                                        \
        for (int k2 = 0; k2 < 4; k2++) {                                         \
            ulonglong2 v0 = qv[2 * k2];                                          \
            ulonglong2 v1 = qv[2 * k2 + 1];                                      \
            asm("fma.rn.f32x2 %0, %1, %2, %0;" : "+l"(a0) : "l"(v0.x), "l"(epk[4*k2+0])); \
            asm("fma.rn.f32x2 %0, %1, %2, %0;" : "+l"(a1) : "l"(v0.y), "l"(epk[4*k2+1])); \
            asm("fma.rn.f32x2 %0, %1, %2, %0;" : "+l"(a2) : "l"(v1.x), "l"(epk[4*k2+2])); \
            asm("fma.rn.f32x2 %0, %1, %2, %0;" : "+l"(a3) : "l"(v1.y), "l"(epk[4*k2+3])); \
        }                                                                        \
        asm("add.rn.f32x2 %0, %0, %1;" : "+l"(a0) : "l"(a1));                    \
        asm("add.rn.f32x2 %0, %0, %1;" : "+l"(a2) : "l"(a3));                    \
        asm("add.rn.f32x2 %0, %0, %1;" : "+l"(a0) : "l"(a2));                    \
        float accf = __uint_as_float((uint32_t)a0) +                             \
                     __uint_as_float((uint32_t)(a0 >> 32));                      \
        float tot = accf + __shfl_xor_sync(0xffffffffu, accf, 16);               \
        float tj = tot * Fv;                                                     \
        float qn = mv ? tj : qreg;                                               \
        if (DOREN) {                                                             \
            int e = (int)((q0w >> 23) & 0xffu) - 127;                            \
            qn *= __int_as_float((127 - e) << 23);                               \
            esum += e;                                                           \
        }                                                                        \
        qreg = qn;                                                               \
        if (h == 0) (QDST)[sidx] = qn;                                           \
        PART_BAR();                                                              \
    } while (0)

    // steps t = 1 .. 2047 (t = 2048 guarded off). Slot of step (1+it*16+gg)
    // is (1+gg)&15 — compile-time. Parity alternates qs0/qs1 by gg.
    #pragma unroll 1
    for (int it = 0; it < 128; it++) {
        const int base = 1 + it * 16;
        #pragma unroll
        for (int gg = 0; gg < 16; gg += 2) {
            int t0 = base + gg;
            if (t0 < SS) { CRF_STEP(qs0, qs1, t0, (1 + gg) & 15, ((gg & 3) == 0)); }
            int t1 = base + gg + 1;
            if (t1 < SS) { CRF_STEP(qs1, qs0, t1, (2 + gg) & 15, 0); }
        }
    }

    // logZ = log(sum_j q_j * exp(end_j)) + esum*ln2
    float v = (h == 0) ? qreg * __expf(endt[j]) : 0.f;
    #pragma unroll
    for (int o = 16; o > 0; o >>= 1)
        v += __shfl_xor_sync(0xffffffffu, v, o);
    if (l == 0) wred[w] = v;
    PART_BAR();   // final barrier (matched by producer)
    if (t == 0)
        g_part[b] = (float)(log((double)(wred[0] + wred[1] + wred[2] + wred[3])) +
                            (double)esum * 0.6931471805599453);

#undef CRF_STEP
}

// ---------------------------------------------------------------------------
// out = mean(partition - score)
// ---------------------------------------------------------------------------
__global__ void crf_final_kernel(float* __restrict__ out)
{
    const int i = threadIdx.x;  // 128 threads
    double v = (double)g_part[i] - (double)g_score[i];
    #pragma unroll
    for (int o = 16; o > 0; o >>= 1)
        v += __shfl_xor_sync(0xffffffffu, v, o);
    __shared__ double sm[4];
    if ((i & 31) == 0) sm[i >> 5] = v;
    __syncthreads();
    if (i == 0)
        out[0] = (float)((sm[0] + sm[1] + sm[2] + sm[3]) * (1.0 / (double)BB));
}

extern "C" void kernel_launch(void* const* d_in, const int* in_sizes, int n_in,
                              void* d_out, int out_size)
{
    const float* em     = (const float*)d_in[0];
    const int* tags     = (const int*)d_in[1];
    const void* mask    = (const void*)d_in[2];
    const float* trans  = (const float*)d_in[3];
    const float* startt = (const float*)d_in[4];
    const float* endt   = (const float*)d_in[5];

    crf_part_score_kernel<<<BB, 192>>>(em, tags, mask, trans, startt, endt);
    crf_final_kernel<<<1, 128>>>((float*)d_out);
}